// round 10
// baseline (speedup 1.0000x reference)
#include <cuda_runtime.h>

// 2x trilinear upsample (TF v1 asymmetric coords, scale = 0.5 per axis).
// Input : [B=2, H=96, W=96, D=48, C=32] f32, channels-last contiguous.
// Output: [B=2, 192, 192, 96, 32] f32.
//
// FINAL (R1 structure): one thread = one input voxel x one float4 channel
// group; loads the 2x2x2 input corner neighborhood (8 float4 up front,
// MLP=8) and writes the 2x2x2 output block (8 float4). 1 load + 1 store per
// output float4 -- compulsory traffic (959MB) at the measured ~6.5TB/s
// write-dominant HBM ceiling. Verified plateau: cache-policy hints, TMA bulk
// stores, traffic-reducing rolling planes, max-occupancy and persistent-grid
// variants all measured equal or slower (150 -> 152/157/168/189us).

#define IN_H 96
#define IN_W 96
#define IN_D 48
#define C4   8          // 32 channels = 8 float4
#define OUT_H 192
#define OUT_W 192
#define OUT_D 96

__device__ __forceinline__ float4 avg4(float4 a, float4 b) {
    return make_float4(0.5f * (a.x + b.x),
                       0.5f * (a.y + b.y),
                       0.5f * (a.z + b.z),
                       0.5f * (a.w + b.w));
}

__global__ __launch_bounds__(256)
void upsample3d_2x_kernel(const float4* __restrict__ in,
                          float4* __restrict__ out) {
    int tid = blockIdx.x * blockDim.x + threadIdx.x;
    // total threads = B * H * W * D * C4 = 2*96*96*48*8 = 7,077,888 (exact grid)

    int c4 = tid & (C4 - 1);
    int t  = tid >> 3;          // C4 == 8
    int d  = t % IN_D;  t /= IN_D;
    int w  = t % IN_W;  t /= IN_W;
    int h  = t % IN_H;
    int b  = t / IN_H;

    int h1 = min(h + 1, IN_H - 1);
    int w1 = min(w + 1, IN_W - 1);
    int d1 = min(d + 1, IN_D - 1);

    // input float4 index
    auto iidx = [&](int hh, int ww, int dd) {
        return (((b * IN_H + hh) * IN_W + ww) * IN_D + dd) * C4 + c4;
    };

    float4 v000 = in[iidx(h,  w,  d )];
    float4 v001 = in[iidx(h,  w,  d1)];
    float4 v010 = in[iidx(h,  w1, d )];
    float4 v011 = in[iidx(h,  w1, d1)];
    float4 v100 = in[iidx(h1, w,  d )];
    float4 v101 = in[iidx(h1, w,  d1)];
    float4 v110 = in[iidx(h1, w1, d )];
    float4 v111 = in[iidx(h1, w1, d1)];

    // D-direction midpoints
    float4 m00 = avg4(v000, v001);
    float4 m01 = avg4(v010, v011);
    float4 m10 = avg4(v100, v101);
    float4 m11 = avg4(v110, v111);

    int oh = 2 * h, ow = 2 * w, od = 2 * d;
    auto oidx = [&](int hh, int ww, int dd) {
        return (((b * OUT_H + hh) * OUT_W + ww) * OUT_D + dd) * C4 + c4;
    };

    // pd = 0 plane (corners at d)
    float4 p01 = avg4(v000, v010);               // (ph=0, pw=1)
    float4 p10 = avg4(v000, v100);               // (ph=1, pw=0)
    float4 p11 = avg4(p01, avg4(v100, v110));    // (ph=1, pw=1)
    out[oidx(oh,     ow,     od)] = v000;
    out[oidx(oh,     ow + 1, od)] = p01;
    out[oidx(oh + 1, ow,     od)] = p10;
    out[oidx(oh + 1, ow + 1, od)] = p11;

    // pd = 1 plane (corners at d midpoints)
    float4 q01 = avg4(m00, m01);
    float4 q10 = avg4(m00, m10);
    float4 q11 = avg4(q01, avg4(m10, m11));
    out[oidx(oh,     ow,     od + 1)] = m00;
    out[oidx(oh,     ow + 1, od + 1)] = q01;
    out[oidx(oh + 1, ow,     od + 1)] = q10;
    out[oidx(oh + 1, ow + 1, od + 1)] = q11;
}

extern "C" void kernel_launch(void* const* d_in, const int* in_sizes, int n_in,
                              void* d_out, int out_size) {
    const float4* in  = (const float4*)d_in[0];
    float4*       out = (float4*)d_out;

    const int total_threads = 2 * IN_H * IN_W * IN_D * C4;  // 7,077,888
    const int block = 256;
    const int grid  = total_threads / block;                 // 27,648 exact

    upsample3d_2x_kernel<<<grid, block>>>(in, out);
}

// round 11
// speedup vs baseline: 1.0025x; 1.0025x over previous
#include <cuda_runtime.h>

// 2x trilinear upsample (TF v1 asymmetric coords, scale = 0.5 per axis).
// Input : [B=2, H=96, W=96, D=48, C=32] f32, channels-last contiguous.
// Output: [B=2, 192, 192, 96, 32] f32.
//
// 256-bit variant of the R1 winner: one thread = one input voxel x one
// 8-channel group (32B). 8x LDG.256 corner loads up front + 8x STG.256,
// halving L1tex wavefront pressure vs the 16B version while keeping the
// same per-SM in-flight byte pool.

#define IN_H 96
#define IN_W 96
#define IN_D 48
#define C8   4          // 32 channels = 4 groups of 8 floats (32B)
#define OUT_H 192
#define OUT_W 192
#define OUT_D 96

struct f8 { float v[8]; };

__device__ __forceinline__ f8 ldg256(const f8* p) {
    f8 r;
    unsigned a0, a1, a2, a3, a4, a5, a6, a7;
    asm volatile("ld.global.nc.v8.b32 {%0,%1,%2,%3,%4,%5,%6,%7}, [%8];"
                 : "=r"(a0), "=r"(a1), "=r"(a2), "=r"(a3),
                   "=r"(a4), "=r"(a5), "=r"(a6), "=r"(a7)
                 : "l"(p));
    r.v[0] = __int_as_float(a0); r.v[1] = __int_as_float(a1);
    r.v[2] = __int_as_float(a2); r.v[3] = __int_as_float(a3);
    r.v[4] = __int_as_float(a4); r.v[5] = __int_as_float(a5);
    r.v[6] = __int_as_float(a6); r.v[7] = __int_as_float(a7);
    return r;
}

__device__ __forceinline__ void stg256(f8* p, const f8& x) {
    asm volatile("st.global.v8.b32 [%0], {%1,%2,%3,%4,%5,%6,%7,%8};"
                 :: "l"(p),
                    "r"(__float_as_int(x.v[0])), "r"(__float_as_int(x.v[1])),
                    "r"(__float_as_int(x.v[2])), "r"(__float_as_int(x.v[3])),
                    "r"(__float_as_int(x.v[4])), "r"(__float_as_int(x.v[5])),
                    "r"(__float_as_int(x.v[6])), "r"(__float_as_int(x.v[7]))
                 : "memory");
}

__device__ __forceinline__ f8 avg8(const f8& a, const f8& b) {
    f8 r;
#pragma unroll
    for (int i = 0; i < 8; i++) r.v[i] = 0.5f * (a.v[i] + b.v[i]);
    return r;
}

__global__ __launch_bounds__(256)
void upsample3d_2x_kernel(const f8* __restrict__ in,
                          f8* __restrict__ out) {
    int tid = blockIdx.x * blockDim.x + threadIdx.x;
    // total threads = B * H * W * D * C8 = 2*96*96*48*4 = 3,538,944 (exact grid)

    int c8 = tid & (C8 - 1);
    int t  = tid >> 2;          // C8 == 4
    int d  = t % IN_D;  t /= IN_D;
    int w  = t % IN_W;  t /= IN_W;
    int h  = t % IN_H;
    int b  = t / IN_H;

    int h1 = min(h + 1, IN_H - 1);
    int w1 = min(w + 1, IN_W - 1);
    int d1 = min(d + 1, IN_D - 1);

    auto iptr = [&](int hh, int ww, int dd) {
        return &in[(((b * IN_H + hh) * IN_W + ww) * IN_D + dd) * C8 + c8];
    };

    f8 v000 = ldg256(iptr(h,  w,  d ));
    f8 v001 = ldg256(iptr(h,  w,  d1));
    f8 v010 = ldg256(iptr(h,  w1, d ));
    f8 v011 = ldg256(iptr(h,  w1, d1));
    f8 v100 = ldg256(iptr(h1, w,  d ));
    f8 v101 = ldg256(iptr(h1, w,  d1));
    f8 v110 = ldg256(iptr(h1, w1, d ));
    f8 v111 = ldg256(iptr(h1, w1, d1));

    // D-direction midpoints
    f8 m00 = avg8(v000, v001);
    f8 m01 = avg8(v010, v011);
    f8 m10 = avg8(v100, v101);
    f8 m11 = avg8(v110, v111);

    int oh = 2 * h, ow = 2 * w, od = 2 * d;
    auto optr = [&](int hh, int ww, int dd) {
        return &out[(((b * OUT_H + hh) * OUT_W + ww) * OUT_D + dd) * C8 + c8];
    };

    // pd = 0 plane (corners at d)
    f8 p01 = avg8(v000, v010);
    f8 p10 = avg8(v000, v100);
    f8 p11 = avg8(p01, avg8(v100, v110));
    stg256(optr(oh,     ow,     od), v000);
    stg256(optr(oh,     ow + 1, od), p01);
    stg256(optr(oh + 1, ow,     od), p10);
    stg256(optr(oh + 1, ow + 1, od), p11);

    // pd = 1 plane (corners at d midpoints)
    f8 q01 = avg8(m00, m01);
    f8 q10 = avg8(m00, m10);
    f8 q11 = avg8(q01, avg8(m10, m11));
    stg256(optr(oh,     ow,     od + 1), m00);
    stg256(optr(oh,     ow + 1, od + 1), q01);
    stg256(optr(oh + 1, ow,     od + 1), q10);
    stg256(optr(oh + 1, ow + 1, od + 1), q11);
}

extern "C" void kernel_launch(void* const* d_in, const int* in_sizes, int n_in,
                              void* d_out, int out_size) {
    const f8* in  = (const f8*)d_in[0];
    f8*       out = (f8*)d_out;

    const int total_threads = 2 * IN_H * IN_W * IN_D * C8;  // 3,538,944
    const int block = 256;
    const int grid  = total_threads / block;                  // 13,824 exact

    upsample3d_2x_kernel<<<grid, block>>>(in, out);
}